// round 7
// baseline (speedup 1.0000x reference)
#include <cuda_runtime.h>
#include <cuda_bf16.h>
#include <math.h>

#define N_NODES 50000
#define D_IN    128
#define D_HID   128
#define D_OUT   64
#define E_FIXED 800000

// ---------------- minimal device scratch (13 MB total) ----------------
// Split-accumulator scheme: the N x 128 layer-1 accumulator lives half in
// d_out (cols 0..63, harness-owned 12.8MB) and half here (cols 64..127).
// g_hi is later reused in place for Q = P @ W2 (N x 64).
__device__ float g_dinv[N_NODES];            // 200 KB: deg^{-1/2}
__device__ float g_hi  [N_NODES * 64];       // 12.8 MB: hi half / Q

__device__ __forceinline__ int clamp_node(int v) {
    return min(max(v, 0), N_NODES - 1);
}

// ---------------- degree / normalization ----------------
__global__ void k_deg_init() {
    int i = blockIdx.x * blockDim.x + threadIdx.x;
    if (i < N_NODES) g_dinv[i] = 1.0f;       // self loop counts once
}

__global__ void k_deg_count(const int* __restrict__ dst, int E) {
    int e = blockIdx.x * blockDim.x + threadIdx.x;
    if (e < E) atomicAdd(&g_dinv[clamp_node(__ldg(dst + e))], 1.0f);
}

__global__ void k_deg_fin() {
    int i = blockIdx.x * blockDim.x + threadIdx.x;
    if (i < N_NODES) g_dinv[i] = rsqrtf(g_dinv[i]);
}

// ---------------- stage A: split self-loop init  acc[i] = x[i] * dinv[i]^2 --
// thread per float4; node = t/32, q = t%32; q<16 -> lo(d_out), else hi(g_hi)
__global__ void k_init_aggx(const float* __restrict__ x, float* __restrict__ lo) {
    int t = blockIdx.x * blockDim.x + threadIdx.x;
    if (t >= N_NODES * 32) return;
    int node = t >> 5, q = t & 31;
    float nn = g_dinv[node]; nn *= nn;
    float4 v = *(const float4*)(x + (size_t)node * 128 + q * 4);
    v.x *= nn; v.y *= nn; v.z *= nn; v.w *= nn;
    float* dstp = (q < 16) ? (lo + (size_t)node * 64 + q * 4)
                           : (g_hi + (size_t)node * 64 + (q - 16) * 4);
    *(float4*)dstp = v;
}

// ---------------- stage B: edge scatter of x into split accumulator --------
__global__ void k_scat_x(const int* __restrict__ src, const int* __restrict__ dst,
                         const float* __restrict__ x, float* __restrict__ lo, int E) {
    int t = blockIdx.x * blockDim.x + threadIdx.x;
    int e = t >> 5, q = t & 31;                       // 32 threads per edge
    if (e >= E) return;
    int s = clamp_node(__ldg(src + e));
    int d = clamp_node(__ldg(dst + e));
    float nrm = g_dinv[s] * g_dinv[d];
    float4 v = *(const float4*)(x + (size_t)s * 128 + q * 4);
    float* p = (q < 16) ? (lo + (size_t)d * 64 + q * 4)
                        : (g_hi + (size_t)d * 64 + (q - 16) * 4);
    atomicAdd(p + 0, v.x * nrm);
    atomicAdd(p + 1, v.y * nrm);
    atomicAdd(p + 2, v.z * nrm);
    atomicAdd(p + 3, v.w * nrm);
}

// ---------------- stage C: P = relu(AGGX @ W1 + b1), in place over split ----
// 256 threads, 32 rows per block, both 64-col halves in one block (row-local).
__global__ __launch_bounds__(256) void k_gemm1(const float* __restrict__ W1,
                                               const float* __restrict__ b1,
                                               float* __restrict__ lo) {
    __shared__ float sX[32][128];      // 16 KB
    __shared__ float sW[128 * 64];     // 32 KB
    const int tid = threadIdx.x;
    const int row0 = blockIdx.x * 32;

    // load X tile from split storage (must be fully staged before overwrite)
    for (int i = tid; i < 32 * 32; i += 256) {
        int r = i >> 5, c = i & 31;
        int row = row0 + r;
        float4 v = make_float4(0.f, 0.f, 0.f, 0.f);
        if (row < N_NODES)
            v = (c < 16) ? *(const float4*)(lo + (size_t)row * 64 + c * 4)
                         : *(const float4*)(g_hi + (size_t)row * 64 + (c - 16) * 4);
        *(float4*)(&sX[r][c * 4]) = v;
    }

    const int warp = tid >> 5, lane = tid & 31;
    float accA[4][2] = {}, accB[4][2] = {};

    #pragma unroll
    for (int half = 0; half < 2; half++) {
        __syncthreads();
        for (int i = tid; i < 128 * 16; i += 256) {    // W half [128 x 64]
            int k = i >> 4, c4 = i & 15;
            ((float4*)sW)[i] = *(const float4*)(W1 + (size_t)k * 128 + half * 64 + c4 * 4);
        }
        __syncthreads();
        #pragma unroll 4
        for (int k = 0; k < 128; k++) {
            float2 wv = *(const float2*)(sW + k * 64 + lane * 2);
            #pragma unroll
            for (int r = 0; r < 4; r++) {
                float xv = sX[warp * 4 + r][k];
                if (half == 0) {
                    accA[r][0] = fmaf(xv, wv.x, accA[r][0]);
                    accA[r][1] = fmaf(xv, wv.y, accA[r][1]);
                } else {
                    accB[r][0] = fmaf(xv, wv.x, accB[r][0]);
                    accB[r][1] = fmaf(xv, wv.y, accB[r][1]);
                }
            }
        }
    }

    float2 bA = *(const float2*)(b1 + lane * 2);
    float2 bB = *(const float2*)(b1 + 64 + lane * 2);
    #pragma unroll
    for (int r = 0; r < 4; r++) {
        int row = row0 + warp * 4 + r;
        if (row < N_NODES) {
            float2 oA = make_float2(fmaxf(accA[r][0] + bA.x, 0.f),
                                    fmaxf(accA[r][1] + bA.y, 0.f));
            float2 oB = make_float2(fmaxf(accB[r][0] + bB.x, 0.f),
                                    fmaxf(accB[r][1] + bB.y, 0.f));
            *(float2*)(lo   + (size_t)row * 64 + lane * 2) = oA;
            *(float2*)(g_hi + (size_t)row * 64 + lane * 2) = oB;
        }
    }
}

// ---------------- stage D: Q = P @ W2, written in place into g_hi ----------
__global__ __launch_bounds__(256) void k_gemm2(const float* __restrict__ W2,
                                               const float* __restrict__ lo) {
    __shared__ float sX[32][128];      // 16 KB
    __shared__ float sW[128 * 64];     // 32 KB
    const int tid = threadIdx.x;
    const int row0 = blockIdx.x * 32;

    for (int i = tid; i < 32 * 32; i += 256) {
        int r = i >> 5, c = i & 31;
        int row = row0 + r;
        float4 v = make_float4(0.f, 0.f, 0.f, 0.f);
        if (row < N_NODES)
            v = (c < 16) ? *(const float4*)(lo + (size_t)row * 64 + c * 4)
                         : *(const float4*)(g_hi + (size_t)row * 64 + (c - 16) * 4);
        *(float4*)(&sX[r][c * 4]) = v;
    }
    for (int i = tid; i < 128 * 16; i += 256) {        // W2 [128 x 64]
        int k = i >> 4, c4 = i & 15;
        ((float4*)sW)[i] = *(const float4*)(W2 + (size_t)k * 64 + c4 * 4);
    }
    __syncthreads();

    const int warp = tid >> 5, lane = tid & 31;
    float acc[4][2] = {};
    #pragma unroll 4
    for (int k = 0; k < 128; k++) {
        float2 wv = *(const float2*)(sW + k * 64 + lane * 2);
        #pragma unroll
        for (int r = 0; r < 4; r++) {
            float xv = sX[warp * 4 + r][k];
            acc[r][0] = fmaf(xv, wv.x, acc[r][0]);
            acc[r][1] = fmaf(xv, wv.y, acc[r][1]);
        }
    }
    #pragma unroll
    for (int r = 0; r < 4; r++) {
        int row = row0 + warp * 4 + r;
        if (row < N_NODES)
            *(float2*)(g_hi + (size_t)row * 64 + lane * 2)
                = make_float2(acc[r][0], acc[r][1]);
    }
}

// ---------------- stage E: self-loop init of layer-2 agg into d_out --------
__global__ void k_init_agg2(float* __restrict__ out) {
    int t = blockIdx.x * blockDim.x + threadIdx.x;     // thread per float4
    if (t >= N_NODES * 16) return;
    int node = t >> 4;
    float nn = g_dinv[node]; nn *= nn;
    float4 v = ((const float4*)g_hi)[t];
    ((float4*)out)[t] = make_float4(v.x * nn, v.y * nn, v.z * nn, v.w * nn);
}

// ---------------- stage F: edge scatter of Q into d_out --------------------
__global__ void k_scat_q(const int* __restrict__ src, const int* __restrict__ dst,
                         float* __restrict__ out, int E) {
    int t = blockIdx.x * blockDim.x + threadIdx.x;
    int e = t >> 4, q = t & 15;                        // 16 threads per edge
    if (e >= E) return;
    int s = clamp_node(__ldg(src + e));
    int d = clamp_node(__ldg(dst + e));
    float nrm = g_dinv[s] * g_dinv[d];
    float4 v = *(const float4*)(g_hi + (size_t)s * 64 + q * 4);
    float* p = out + (size_t)d * 64 + q * 4;
    atomicAdd(p + 0, v.x * nrm);
    atomicAdd(p + 1, v.y * nrm);
    atomicAdd(p + 2, v.z * nrm);
    atomicAdd(p + 3, v.w * nrm);
}

// ---------------- stage G: bias + log_softmax in place (width 64) ----------
__global__ void k_logsoftmax(const float* __restrict__ b2, float* __restrict__ out) {
    int node = blockIdx.x * (blockDim.x / 32) + (threadIdx.x >> 5);
    int lane = threadIdx.x & 31;
    if (node >= N_NODES) return;
    float2 v  = ((float2*)(out + (size_t)node * 64))[lane];
    float2 bb = ((const float2*)b2)[lane];
    v.x += bb.x; v.y += bb.y;
    float m = fmaxf(v.x, v.y);
    #pragma unroll
    for (int o = 16; o; o >>= 1) m = fmaxf(m, __shfl_xor_sync(0xFFFFFFFFu, m, o));
    float s = __expf(v.x - m) + __expf(v.y - m);
    #pragma unroll
    for (int o = 16; o; o >>= 1) s += __shfl_xor_sync(0xFFFFFFFFu, s, o);
    float l = m + __logf(s);
    ((float2*)(out + (size_t)node * 64))[lane] = make_float2(v.x - l, v.y - l);
}

// ---------------- launch ----------------
extern "C" void kernel_launch(void* const* d_in, const int* in_sizes, int n_in,
                              void* d_out, int out_size) {
    const float* x  = (const float*)d_in[0];
    const int*   ei = (const int*)d_in[1];        // int64 ref -> int32 delivered
    const float* W1 = (const float*)d_in[2];
    const float* b1 = (const float*)d_in[3];
    const float* W2 = (const float*)d_in[4];
    const float* b2 = (const float*)d_in[5];
    float* out = (float*)d_out;

    const int E = in_sizes[1] / 2;
    const int* src = ei;
    const int* dst = ei + E;

    const int TB = 256;

    // 1) degree + d^{-1/2}
    k_deg_init <<<(N_NODES + TB - 1) / TB, TB>>>();
    k_deg_count<<<(E + TB - 1) / TB, TB>>>(dst, E);
    k_deg_fin  <<<(N_NODES + TB - 1) / TB, TB>>>();

    // 2) AGGX = Â·x  (split accumulator: d_out = cols 0..63, g_hi = 64..127)
    k_init_aggx<<<(N_NODES * 32 + TB - 1) / TB, TB>>>(x, out);
    {
        long long t = (long long)E * 32;
        k_scat_x<<<(int)((t + TB - 1) / TB), TB>>>(src, dst, x, out, E);
    }

    // 3) P = relu(AGGX @ W1 + b1)   in place over split storage
    k_gemm1<<<(N_NODES + 31) / 32, TB>>>(W1, b1, out);

    // 4) Q = P @ W2   -> g_hi (in place, row-local)
    k_gemm2<<<(N_NODES + 31) / 32, TB>>>(W2, out);

    // 5) d_out = Â·Q  (self-loop init + edge scatter)
    k_init_agg2<<<(N_NODES * 16 + TB - 1) / TB, TB>>>(out);
    {
        long long t = (long long)E * 16;
        k_scat_q<<<(int)((t + TB - 1) / TB), TB>>>(src, dst, out, E);
    }

    // 6) out = log_softmax(out + b2)
    k_logsoftmax<<<(N_NODES * 32 + TB - 1) / TB, TB>>>(b2, out);
}

// round 8
// speedup vs baseline: 1.7965x; 1.7965x over previous
#include <cuda_runtime.h>
#include <cuda_bf16.h>
#include <math.h>

#define N_NODES 50000
#define D_IN    128
#define D_HID   128
#define D_OUT   64

// ---------------- minimal device scratch (13 MB total) ----------------
// Split-accumulator scheme: the N x 128 layer-1 accumulator lives half in
// d_out (cols 0..63, harness-owned 12.8MB) and half here (cols 64..127).
// g_hi is later reused in place for Q = P @ W2 (N x 64).
__device__ float g_dinv[N_NODES];            // 200 KB: deg^{-1/2}
__device__ float g_hi  [N_NODES * 64];       // 12.8 MB: hi half / Q

__device__ __forceinline__ int clamp_node(int v) {
    return min(max(v, 0), N_NODES - 1);
}

__device__ __forceinline__ void red_add_v4(float* p, float a, float b, float c, float d) {
    asm volatile("red.global.add.v4.f32 [%0], {%1,%2,%3,%4};"
                 :: "l"(p), "f"(a), "f"(b), "f"(c), "f"(d) : "memory");
}

// ---------------- degree / normalization ----------------
__global__ void k_deg_init() {
    int i = blockIdx.x * blockDim.x + threadIdx.x;
    if (i < N_NODES) g_dinv[i] = 1.0f;       // self loop counts once
}

__global__ void k_deg_count(const int* __restrict__ dst, int E) {
    int e = blockIdx.x * blockDim.x + threadIdx.x;
    if (e < E) atomicAdd(&g_dinv[clamp_node(__ldg(dst + e))], 1.0f);
}

__global__ void k_deg_fin() {
    int i = blockIdx.x * blockDim.x + threadIdx.x;
    if (i < N_NODES) g_dinv[i] = rsqrtf(g_dinv[i]);
}

// ---------------- stage A: split self-loop init  acc[i] = x[i] * dinv[i]^2 --
__global__ void k_init_aggx(const float* __restrict__ x, float* __restrict__ lo) {
    int t = blockIdx.x * blockDim.x + threadIdx.x;
    if (t >= N_NODES * 32) return;
    int node = t >> 5, q = t & 31;
    float nn = g_dinv[node]; nn *= nn;
    float4 v = *(const float4*)(x + (size_t)node * 128 + q * 4);
    v.x *= nn; v.y *= nn; v.z *= nn; v.w *= nn;
    float* dstp = (q < 16) ? (lo + (size_t)node * 64 + q * 4)
                           : (g_hi + (size_t)node * 64 + (q - 16) * 4);
    *(float4*)dstp = v;
}

// ---------------- stage B: edge scatter of x into split accumulator --------
__global__ void k_scat_x(const int* __restrict__ src, const int* __restrict__ dst,
                         const float* __restrict__ x, float* __restrict__ lo, int E) {
    int t = blockIdx.x * blockDim.x + threadIdx.x;
    int e = t >> 5, q = t & 31;                       // 32 threads per edge
    if (e >= E) return;
    int s = clamp_node(__ldg(src + e));
    int d = clamp_node(__ldg(dst + e));
    float nrm = g_dinv[s] * g_dinv[d];
    float4 v = *(const float4*)(x + (size_t)s * 128 + q * 4);
    float* p = (q < 16) ? (lo + (size_t)d * 64 + q * 4)
                        : (g_hi + (size_t)d * 64 + (q - 16) * 4);
    red_add_v4(p, v.x * nrm, v.y * nrm, v.z * nrm, v.w * nrm);
}

// ---------------- stage C: P = relu(AGGX @ W1 + b1), in place over split ----
__global__ __launch_bounds__(256) void k_gemm1(const float* __restrict__ W1,
                                               const float* __restrict__ b1,
                                               float* __restrict__ lo) {
    __shared__ float sX[32][128];      // 16 KB
    __shared__ float sW[128 * 64];     // 32 KB
    const int tid = threadIdx.x;
    const int row0 = blockIdx.x * 32;

    for (int i = tid; i < 32 * 32; i += 256) {
        int r = i >> 5, c = i & 31;
        int row = row0 + r;
        float4 v = make_float4(0.f, 0.f, 0.f, 0.f);
        if (row < N_NODES)
            v = (c < 16) ? *(const float4*)(lo + (size_t)row * 64 + c * 4)
                         : *(const float4*)(g_hi + (size_t)row * 64 + (c - 16) * 4);
        *(float4*)(&sX[r][c * 4]) = v;
    }

    const int warp = tid >> 5, lane = tid & 31;
    float accA[4][2] = {}, accB[4][2] = {};

    #pragma unroll
    for (int half = 0; half < 2; half++) {
        __syncthreads();
        for (int i = tid; i < 128 * 16; i += 256) {    // W half [128 x 64]
            int k = i >> 4, c4 = i & 15;
            ((float4*)sW)[i] = *(const float4*)(W1 + (size_t)k * 128 + half * 64 + c4 * 4);
        }
        __syncthreads();
        #pragma unroll 4
        for (int k = 0; k < 128; k++) {
            float2 wv = *(const float2*)(sW + k * 64 + lane * 2);
            #pragma unroll
            for (int r = 0; r < 4; r++) {
                float xv = sX[warp * 4 + r][k];
                if (half == 0) {
                    accA[r][0] = fmaf(xv, wv.x, accA[r][0]);
                    accA[r][1] = fmaf(xv, wv.y, accA[r][1]);
                } else {
                    accB[r][0] = fmaf(xv, wv.x, accB[r][0]);
                    accB[r][1] = fmaf(xv, wv.y, accB[r][1]);
                }
            }
        }
    }

    float2 bA = *(const float2*)(b1 + lane * 2);
    float2 bB = *(const float2*)(b1 + 64 + lane * 2);
    #pragma unroll
    for (int r = 0; r < 4; r++) {
        int row = row0 + warp * 4 + r;
        if (row < N_NODES) {
            float2 oA = make_float2(fmaxf(accA[r][0] + bA.x, 0.f),
                                    fmaxf(accA[r][1] + bA.y, 0.f));
            float2 oB = make_float2(fmaxf(accB[r][0] + bB.x, 0.f),
                                    fmaxf(accB[r][1] + bB.y, 0.f));
            *(float2*)(lo   + (size_t)row * 64 + lane * 2) = oA;
            *(float2*)(g_hi + (size_t)row * 64 + lane * 2) = oB;
        }
    }
}

// ---------------- stage D: Q = P @ W2, written in place into g_hi ----------
__global__ __launch_bounds__(256) void k_gemm2(const float* __restrict__ W2,
                                               const float* __restrict__ lo) {
    __shared__ float sX[32][128];      // 16 KB
    __shared__ float sW[128 * 64];     // 32 KB
    const int tid = threadIdx.x;
    const int row0 = blockIdx.x * 32;

    for (int i = tid; i < 32 * 32; i += 256) {
        int r = i >> 5, c = i & 31;
        int row = row0 + r;
        float4 v = make_float4(0.f, 0.f, 0.f, 0.f);
        if (row < N_NODES)
            v = (c < 16) ? *(const float4*)(lo + (size_t)row * 64 + c * 4)
                         : *(const float4*)(g_hi + (size_t)row * 64 + (c - 16) * 4);
        *(float4*)(&sX[r][c * 4]) = v;
    }
    for (int i = tid; i < 128 * 16; i += 256) {        // W2 [128 x 64]
        int k = i >> 4, c4 = i & 15;
        ((float4*)sW)[i] = *(const float4*)(W2 + (size_t)k * 64 + c4 * 4);
    }
    __syncthreads();

    const int warp = tid >> 5, lane = tid & 31;
    float acc[4][2] = {};
    #pragma unroll 4
    for (int k = 0; k < 128; k++) {
        float2 wv = *(const float2*)(sW + k * 64 + lane * 2);
        #pragma unroll
        for (int r = 0; r < 4; r++) {
            float xv = sX[warp * 4 + r][k];
            acc[r][0] = fmaf(xv, wv.x, acc[r][0]);
            acc[r][1] = fmaf(xv, wv.y, acc[r][1]);
        }
    }
    #pragma unroll
    for (int r = 0; r < 4; r++) {
        int row = row0 + warp * 4 + r;
        if (row < N_NODES)
            *(float2*)(g_hi + (size_t)row * 64 + lane * 2)
                = make_float2(acc[r][0], acc[r][1]);
    }
}

// ---------------- stage E: self-loop init of layer-2 agg into d_out --------
__global__ void k_init_agg2(float* __restrict__ out) {
    int t = blockIdx.x * blockDim.x + threadIdx.x;     // thread per float4
    if (t >= N_NODES * 16) return;
    int node = t >> 4;
    float nn = g_dinv[node]; nn *= nn;
    float4 v = ((const float4*)g_hi)[t];
    ((float4*)out)[t] = make_float4(v.x * nn, v.y * nn, v.z * nn, v.w * nn);
}

// ---------------- stage F: edge scatter of Q into d_out --------------------
__global__ void k_scat_q(const int* __restrict__ src, const int* __restrict__ dst,
                         float* __restrict__ out, int E) {
    int t = blockIdx.x * blockDim.x + threadIdx.x;
    int e = t >> 4, q = t & 15;                        // 16 threads per edge
    if (e >= E) return;
    int s = clamp_node(__ldg(src + e));
    int d = clamp_node(__ldg(dst + e));
    float nrm = g_dinv[s] * g_dinv[d];
    float4 v = *(const float4*)(g_hi + (size_t)s * 64 + q * 4);
    float* p = out + (size_t)d * 64 + q * 4;
    red_add_v4(p, v.x * nrm, v.y * nrm, v.z * nrm, v.w * nrm);
}

// ---------------- stage G: bias + log_softmax in place (width 64) ----------
__global__ void k_logsoftmax(const float* __restrict__ b2, float* __restrict__ out) {
    int node = blockIdx.x * (blockDim.x / 32) + (threadIdx.x >> 5);
    int lane = threadIdx.x & 31;
    if (node >= N_NODES) return;
    float2 v  = ((float2*)(out + (size_t)node * 64))[lane];
    float2 bb = ((const float2*)b2)[lane];
    v.x += bb.x; v.y += bb.y;
    float m = fmaxf(v.x, v.y);
    #pragma unroll
    for (int o = 16; o; o >>= 1) m = fmaxf(m, __shfl_xor_sync(0xFFFFFFFFu, m, o));
    float s = __expf(v.x - m) + __expf(v.y - m);
    #pragma unroll
    for (int o = 16; o; o >>= 1) s += __shfl_xor_sync(0xFFFFFFFFu, s, o);
    float l = m + __logf(s);
    ((float2*)(out + (size_t)node * 64))[lane] = make_float2(v.x - l, v.y - l);
}

// ---------------- launch ----------------
extern "C" void kernel_launch(void* const* d_in, const int* in_sizes, int n_in,
                              void* d_out, int out_size) {
    const float* x  = (const float*)d_in[0];
    const int*   ei = (const int*)d_in[1];        // int64 ref -> int32 delivered
    const float* W1 = (const float*)d_in[2];
    const float* b1 = (const float*)d_in[3];
    const float* W2 = (const float*)d_in[4];
    const float* b2 = (const float*)d_in[5];
    float* out = (float*)d_out;

    const int E = in_sizes[1] / 2;
    const int* src = ei;
    const int* dst = ei + E;

    const int TB = 256;

    // 1) degree + d^{-1/2}
    k_deg_init <<<(N_NODES + TB - 1) / TB, TB>>>();
    k_deg_count<<<(E + TB - 1) / TB, TB>>>(dst, E);
    k_deg_fin  <<<(N_NODES + TB - 1) / TB, TB>>>();

    // 2) AGGX = Â·x  (split accumulator: d_out = cols 0..63, g_hi = 64..127)
    k_init_aggx<<<(N_NODES * 32 + TB - 1) / TB, TB>>>(x, out);
    {
        long long t = (long long)E * 32;
        k_scat_x<<<(int)((t + TB - 1) / TB), TB>>>(src, dst, x, out, E);
    }

    // 3) P = relu(AGGX @ W1 + b1)   in place over split storage
    k_gemm1<<<(N_NODES + 31) / 32, TB>>>(W1, b1, out);

    // 4) Q = P @ W2   -> g_hi (in place, row-local)
    k_gemm2<<<(N_NODES + 31) / 32, TB>>>(W2, out);

    // 5) d_out = Â·Q  (self-loop init + edge scatter)
    k_init_agg2<<<(N_NODES * 16 + TB - 1) / TB, TB>>>(out);
    {
        long long t = (long long)E * 16;
        k_scat_q<<<(int)((t + TB - 1) / TB), TB>>>(src, dst, out, E);
    }

    // 6) out = log_softmax(out + b2)
    k_logsoftmax<<<(N_NODES * 32 + TB - 1) / TB, TB>>>(b2, out);
}